// round 13
// baseline (speedup 1.0000x reference)
#include <cuda_runtime.h>
#include <cstdint>

// ---------------------------------------------------------------------------
// PolicyHead fused kernel v8: one block per image, 768 threads, 24 warps.
//   y[361x64] = x[361x256] @ [w_p*ivp | w_g*ivg]   (mma.sync tf32, fp32 accum)
//   g: relu(y_g + cg) -> mean/max pool -> bias, pass logits
//   p: relu(y_p + cp) @ w_out -> pi_main / pi_aux
// A: raw fp32 via cp.async (HW truncates to tf32 in MMA); B: RNA tf32 init.
// 3-stage pipeline, K-chunk 32, per chunk: wait_group 1 ; sync ; issue(c+2) ;
// compute(c). B streamed per-chunk from global (L2-hot) into 3 small stages.
// Warps: wm = w>>1 (0..11) owns m-tiles {wm, wm+12}; wq = w&1 N-half.
// ---------------------------------------------------------------------------

#define NIMG    2048
#define HW      361
#define OUTW    362
#define AUXOFF  (NIMG * OUTW)
#define EPSF    1e-3f

// shared memory word offsets
#define ASTAGE   13824        // one A stage: 384 rows * 36 words
#define BSTAGE   2304         // one B stage: 64 rows * 36 words
#define OFF_BS   41472        // 3 B stages = 6912 words
#define OFF_WB   48384        // 2048
#define OFF_WO   50432        // 64
#define OFF_CG   50496        // 32
#define OFF_CP   50528        // 32
#define OFF_POOL 50560        // 64
#define OFF_RS   50624        // 12*32
#define OFF_RM   51008        // 12*32
#define SMEM_WORDS 51392
#define SMEM_BYTES (SMEM_WORDS * 4)   // 205,568 B

__device__ __align__(16) uint32_t g_Bt[64 * 256];  // BN-folded, [n][k], tf32

__device__ __forceinline__ uint32_t f2tf32(float f) {
    uint32_t u;
    asm("cvt.rna.tf32.f32 %0, %1;" : "=r"(u) : "f"(f));
    return u;
}

__device__ __forceinline__ void mma_tf32(float c[4],
                                         uint32_t a0, uint32_t a1,
                                         uint32_t a2, uint32_t a3,
                                         uint32_t b0, uint32_t b1) {
    asm volatile(
        "mma.sync.aligned.m16n8k8.row.col.f32.tf32.tf32.f32 "
        "{%0,%1,%2,%3}, {%4,%5,%6,%7}, {%8,%9}, {%0,%1,%2,%3};"
        : "+f"(c[0]), "+f"(c[1]), "+f"(c[2]), "+f"(c[3])
        : "r"(a0), "r"(a1), "r"(a2), "r"(a3), "r"(b0), "r"(b1));
}

__device__ __forceinline__ void ldsm4(uint32_t& r0, uint32_t& r1,
                                      uint32_t& r2, uint32_t& r3, uint32_t addr) {
    asm volatile("ldmatrix.sync.aligned.m8n8.x4.shared.b16 {%0,%1,%2,%3}, [%4];"
                 : "=r"(r0), "=r"(r1), "=r"(r2), "=r"(r3) : "r"(addr));
}

__device__ __forceinline__ void cpa16(uint32_t dst, const void* src) {
    asm volatile("cp.async.cg.shared.global [%0], [%1], 16;"
                 :: "r"(dst), "l"(src) : "memory");
}

// ---- init: fold BN inverse-std, transpose to [n][k], convert to tf32 -------
__global__ void policy_init(const float* __restrict__ w_p,
                            const float* __restrict__ w_g,
                            const float* __restrict__ var_p,
                            const float* __restrict__ var_g) {
    int i = blockIdx.x * 256 + threadIdx.x;   // 0..16383
    int n = i >> 8, k = i & 255;
    float v = (n < 32)
        ? w_p[k * 32 + n] * rsqrtf(var_p[n] + EPSF)
        : w_g[k * 32 + (n - 32)] * rsqrtf(var_g[n - 32] + EPSF);
    g_Bt[i] = f2tf32(v);
}

__global__ void __launch_bounds__(768, 1) policy_head_kernel(
    const float* __restrict__ x,
    const float* __restrict__ beta_g, const float* __restrict__ mean_g,
    const float* __restrict__ var_g,
    const float* __restrict__ w_bias, const float* __restrict__ b_bias,
    const float* __restrict__ beta_p, const float* __restrict__ mean_p,
    const float* __restrict__ var_p,
    const float* __restrict__ w_out,
    const float* __restrict__ w_pass, const float* __restrict__ b_pass,
    float* __restrict__ out)
{
    extern __shared__ uint32_t sm[];
    float* smf = reinterpret_cast<float*>(sm);

    const int tid  = threadIdx.x;
    const int lane = tid & 31;
    const int w    = tid >> 5;          // warp 0..23
    const int q    = lane & 3;
    const int g    = lane >> 2;
    const int wm   = w >> 1;            // M-warp 0..11 -> m-tiles wm, wm+12
    const int wq   = w & 1;             // N-half: 0=p, 1=g
    const int img  = blockIdx.x;
    const int imgBase = img * HW;
    const float4* x4 = reinterpret_cast<const float4*>(x);
    const uint32_t smb = (uint32_t)__cvta_generic_to_shared(sm);

    // ldmatrix per-lane offsets (words, within a stage)
    const uint32_t aFrag = (uint32_t)((lane & 15) * 36 + ((lane & 16) ? 4 : 0));
    const uint32_t bFrag = (uint32_t)((wq * 32 + (lane & 15)) * 36 +
                                      ((lane & 16) ? 4 : 0));

    // ---- prologue: group 0 = A(0) + B(0) + w_bias ---------------------------
#pragma unroll
    for (int it = 0; it < 4; ++it) {
        int idx = tid + it * 768;               // 0..3071
        int r = idx >> 3, c8 = idx & 7;
        if (r < HW)
            cpa16(smb + 4u * (uint32_t)(r * 36 + c8 * 4),
                  x4 + (imgBase + r) * 64 + c8);
    }
    if (tid < 512) {
        int n = tid >> 3, seg = tid & 7;
        cpa16(smb + 4u * (uint32_t)(OFF_BS + n * 36 + seg * 4),
              g_Bt + n * 256 + seg * 4);
        cpa16(smb + (uint32_t)((OFF_WB + tid * 4) * 4), w_bias + tid * 4);
    }
    asm volatile("cp.async.commit_group;" ::: "memory");

    // ---- group 1 = A(1) + B(1) ----------------------------------------------
#pragma unroll
    for (int it = 0; it < 4; ++it) {
        int idx = tid + it * 768;
        int r = idx >> 3, c8 = idx & 7;
        if (r < HW)
            cpa16(smb + 4u * (uint32_t)(ASTAGE + r * 36 + c8 * 4),
                  x4 + (imgBase + r) * 64 + 8 + c8);
    }
    if (tid < 512) {
        int n = tid >> 3, seg = tid & 7;
        cpa16(smb + 4u * (uint32_t)(OFF_BS + BSTAGE + n * 36 + seg * 4),
              g_Bt + n * 256 + 32 + seg * 4);
    }
    asm volatile("cp.async.commit_group;" ::: "memory");

    // zero-pad rows 361..383 of all 3 A stages (cp.async never touches them)
    for (int i = tid; i < 3 * 23 * 36; i += 768) {
        int st = i / (23 * 36), rem = i % (23 * 36);
        sm[st * ASTAGE + (361 + rem / 36) * 36 + rem % 36] = 0;
    }

    if (tid < 32) {
        smf[OFF_WO + tid]      = w_out[tid * 2];
        smf[OFF_WO + 32 + tid] = w_out[tid * 2 + 1];
        smf[OFF_CG + tid] = beta_g[tid] - mean_g[tid] * rsqrtf(var_g[tid] + EPSF);
    }

    float acc[2][4][4];
#pragma unroll
    for (int m = 0; m < 2; ++m)
#pragma unroll
        for (int n = 0; n < 4; ++n)
#pragma unroll
            for (int j = 0; j < 4; ++j) acc[m][n][j] = 0.f;

    // ---- main loop: 8 K-chunks of 32, 3-stage, ONE barrier per chunk -------
    for (int c = 0; c < 8; ++c) {
        asm volatile("cp.async.wait_group 1;" ::: "memory");  // chunk c resident
        __syncthreads();   // data visible; stage (c+2)%3 free (compute c-1 done)

        if (c + 2 < 8) {   // issue chunk c+2 — keeps 2 chunks in flight
            const int cc = c + 2;
            const uint32_t ast = (uint32_t)(cc % 3) * ASTAGE;
#pragma unroll
            for (int it = 0; it < 4; ++it) {
                int idx = tid + it * 768;
                int r = idx >> 3, c8 = idx & 7;
                if (r < HW)
                    cpa16(smb + 4u * (ast + (uint32_t)(r * 36 + c8 * 4)),
                          x4 + (imgBase + r) * 64 + cc * 8 + c8);
            }
            if (tid < 512) {
                int n = tid >> 3, seg = tid & 7;
                cpa16(smb + 4u * (uint32_t)(OFF_BS + (cc % 3) * BSTAGE
                                            + n * 36 + seg * 4),
                      g_Bt + n * 256 + cc * 32 + seg * 4);
            }
        }
        asm volatile("cp.async.commit_group;" ::: "memory");  // uniform count

        const uint32_t aBase = smb + 4u * ((uint32_t)(c % 3) * ASTAGE + aFrag);
        const uint32_t bBase = smb + 4u * ((uint32_t)(OFF_BS + (c % 3) * BSTAGE)
                                           + bFrag);
#pragma unroll
        for (int s = 0; s < 4; ++s) {
            const uint32_t bA = bBase + (uint32_t)(s * 32);
            uint32_t b0[4], b1[4];
            ldsm4(b0[0], b0[1], b1[0], b1[1], bA);                    // n-tiles 0,1
            ldsm4(b0[2], b0[3], b1[2], b1[3], bA + 4u * 16 * 36);     // n-tiles 2,3
#pragma unroll
            for (int m = 0; m < 2; ++m) {
                uint32_t a0, a1, a2, a3;
                ldsm4(a0, a1, a2, a3,
                      aBase + 4u * (uint32_t)((wm + m * 12) * 16 * 36 + s * 8));
#pragma unroll
                for (int nt = 0; nt < 4; ++nt)
                    mma_tf32(acc[m][nt], a0, a1, a2, a3, b0[nt], b1[nt]);
            }
        }
    }

    // ---- g-branch pooling (wq==1 warps own g channels) ----------------------
    if (wq == 1) {
#pragma unroll
        for (int nt = 0; nt < 4; ++nt) {
#pragma unroll
            for (int j = 0; j < 2; ++j) {
                int ch = nt * 8 + 2 * q + j;
                float cg = smf[OFF_CG + ch];
                float s = 0.f, mx = 0.f;
#pragma unroll
                for (int m = 0; m < 2; ++m) {
                    int r0 = (wm + m * 12) * 16 + g;
                    float v0 = fmaxf(acc[m][nt][j] + cg, 0.f);
                    float v1 = fmaxf(acc[m][nt][2 + j] + cg, 0.f);
                    if (r0 >= HW) v0 = 0.f;
                    if (r0 + 8 >= HW) v1 = 0.f;
                    s += v0 + v1;
                    mx = fmaxf(mx, fmaxf(v0, v1));
                }
#pragma unroll
                for (int o = 4; o <= 16; o <<= 1) {
                    s += __shfl_xor_sync(0xffffffffu, s, o);
                    mx = fmaxf(mx, __shfl_xor_sync(0xffffffffu, mx, o));
                }
                if (g == 0) {
                    smf[OFF_RS + wm * 32 + ch] = s;
                    smf[OFF_RM + wm * 32 + ch] = mx;
                }
            }
        }
    }
    __syncthreads();

    // ---- warp 0: pooled bias, cp offset, pass logits ------------------------
    if (w == 0) {
        float s = 0.f, mx = 0.f;
#pragma unroll
        for (int wi = 0; wi < 12; ++wi) {
            s += smf[OFF_RS + wi * 32 + lane];
            mx = fmaxf(mx, smf[OFF_RM + wi * 32 + lane]);
        }
        smf[OFF_POOL + lane]      = s * (1.f / 361.f);
        smf[OFF_POOL + 32 + lane] = mx;
        __syncwarp();

        float bias = b_bias[lane];
#pragma unroll
        for (int j = 0; j < 64; ++j)
            bias += smf[OFF_POOL + j] * smf[OFF_WB + j * 32 + lane];
        float ivp = rsqrtf(var_p[lane] + EPSF);
        smf[OFF_CP + lane] = (bias - mean_p[lane]) * ivp + beta_p[lane];

        if (lane < 2) {
            float pv = b_pass[lane] - 3.0f;
#pragma unroll
            for (int j = 0; j < 64; ++j)
                pv += smf[OFF_POOL + j] * w_pass[j * 2 + lane];
            out[(lane ? AUXOFF : 0) + img * OUTW + HW] = pv;
        }
    }
    __syncthreads();

    // ---- p-branch epilogue (wq==0 warps own p channels) ---------------------
    if (wq == 0) {
#pragma unroll
        for (int m = 0; m < 2; ++m) {
            int mt = wm + m * 12;
#pragma unroll
            for (int h = 0; h < 2; ++h) {
                int r = mt * 16 + g + 8 * h;
                float p0 = 0.f, p1 = 0.f;
#pragma unroll
                for (int nt = 0; nt < 4; ++nt) {
#pragma unroll
                    for (int j = 0; j < 2; ++j) {
                        int ch = nt * 8 + 2 * q + j;
                        float vv = fmaxf(acc[m][nt][2 * h + j] + smf[OFF_CP + ch], 0.f);
                        p0 += vv * smf[OFF_WO + ch];
                        p1 += vv * smf[OFF_WO + 32 + ch];
                    }
                }
                p0 += __shfl_xor_sync(0xffffffffu, p0, 1);
                p0 += __shfl_xor_sync(0xffffffffu, p0, 2);
                p1 += __shfl_xor_sync(0xffffffffu, p1, 1);
                p1 += __shfl_xor_sync(0xffffffffu, p1, 2);
                if (q == 0 && r < HW) {
                    out[img * OUTW + r]          = p0;
                    out[AUXOFF + img * OUTW + r] = p1;
                }
            }
        }
    }
}

extern "C" void kernel_launch(void* const* d_in, const int* in_sizes, int n_in,
                              void* d_out, int out_size) {
    (void)in_sizes; (void)n_in; (void)out_size;
    policy_init<<<64, 256>>>(
        (const float*)d_in[1], (const float*)d_in[2],
        (const float*)d_in[10], (const float*)d_in[5]);
    cudaFuncSetAttribute(policy_head_kernel,
                         cudaFuncAttributeMaxDynamicSharedMemorySize, SMEM_BYTES);
    policy_head_kernel<<<NIMG, 768, SMEM_BYTES>>>(
        (const float*)d_in[0],
        (const float*)d_in[3],  (const float*)d_in[4],  (const float*)d_in[5],
        (const float*)d_in[6],  (const float*)d_in[7],  (const float*)d_in[8],
        (const float*)d_in[9],  (const float*)d_in[10], (const float*)d_in[11],
        (const float*)d_in[12], (const float*)d_in[13],
        (float*)d_out);
}

// round 15
// speedup vs baseline: 1.0672x; 1.0672x over previous
#include <cuda_runtime.h>
#include <cstdint>

// ---------------------------------------------------------------------------
// PolicyHead fused kernel v9b: one block per image, 384 threads, 12 warps.
//   y[361x64] = x[361x256] @ [w_p*ivp | w_g*ivg]   (mma.sync tf32, fp32 accum)
//   g: relu(y_g + cg) -> mean/max pool -> bias, pass logits
//   p: relu(y_p + cp) @ w_out -> pi_main / pi_aux
// A: raw fp32 via cp.async (HW truncates to tf32 in MMA); B: RNA tf32 init.
// Warp grid Wm=12 x Wn=1: warp w owns m-tiles {w, w+12} and ALL 8 n-tiles.
// v9b fixes the Bt prologue copy (64 rows x 64 segs of 16B; v9 copied 16 segs).
// ---------------------------------------------------------------------------

#define NIMG    2048
#define HW      361
#define OUTW    362
#define AUXOFF  (NIMG * OUTW)
#define EPSF    1e-3f

// shared memory word offsets
#define ASTAGE   13824        // one A stage: 384 rows * 36 words
#define OFF_B    27648        // Bt: 64 rows * 260 words = 16640
#define OFF_WB   44288        // 2048
#define OFF_WO   46336        // 64
#define OFF_CG   46400        // 32
#define OFF_CP   46432        // 32
#define OFF_POOL 46464        // 64
#define OFF_RS   46528        // 12*32
#define OFF_RM   46912        // 12*32
#define SMEM_WORDS 47296
#define SMEM_BYTES (SMEM_WORDS * 4)   // 189,184 B

__device__ __align__(16) uint32_t g_Bt[64 * 256];  // BN-folded, [n][k], tf32

__device__ __forceinline__ uint32_t f2tf32(float f) {
    uint32_t u;
    asm("cvt.rna.tf32.f32 %0, %1;" : "=r"(u) : "f"(f));
    return u;
}

__device__ __forceinline__ void mma_tf32(float c[4],
                                         uint32_t a0, uint32_t a1,
                                         uint32_t a2, uint32_t a3,
                                         uint32_t b0, uint32_t b1) {
    asm volatile(
        "mma.sync.aligned.m16n8k8.row.col.f32.tf32.tf32.f32 "
        "{%0,%1,%2,%3}, {%4,%5,%6,%7}, {%8,%9}, {%0,%1,%2,%3};"
        : "+f"(c[0]), "+f"(c[1]), "+f"(c[2]), "+f"(c[3])
        : "r"(a0), "r"(a1), "r"(a2), "r"(a3), "r"(b0), "r"(b1));
}

__device__ __forceinline__ void ldsm4(uint32_t& r0, uint32_t& r1,
                                      uint32_t& r2, uint32_t& r3, uint32_t addr) {
    asm volatile("ldmatrix.sync.aligned.m8n8.x4.shared.b16 {%0,%1,%2,%3}, [%4];"
                 : "=r"(r0), "=r"(r1), "=r"(r2), "=r"(r3) : "r"(addr));
}

__device__ __forceinline__ void cpa16(uint32_t dst, const void* src) {
    asm volatile("cp.async.cg.shared.global [%0], [%1], 16;"
                 :: "r"(dst), "l"(src) : "memory");
}

// ---- init: fold BN inverse-std, transpose to [n][k], convert to tf32 -------
__global__ void policy_init(const float* __restrict__ w_p,
                            const float* __restrict__ w_g,
                            const float* __restrict__ var_p,
                            const float* __restrict__ var_g) {
    int i = blockIdx.x * 256 + threadIdx.x;   // 0..16383
    int n = i >> 8, k = i & 255;
    float v = (n < 32)
        ? w_p[k * 32 + n] * rsqrtf(var_p[n] + EPSF)
        : w_g[k * 32 + (n - 32)] * rsqrtf(var_g[n - 32] + EPSF);
    g_Bt[i] = f2tf32(v);
}

__global__ void __launch_bounds__(384, 1) policy_head_kernel(
    const float* __restrict__ x,
    const float* __restrict__ beta_g, const float* __restrict__ mean_g,
    const float* __restrict__ var_g,
    const float* __restrict__ w_bias, const float* __restrict__ b_bias,
    const float* __restrict__ beta_p, const float* __restrict__ mean_p,
    const float* __restrict__ var_p,
    const float* __restrict__ w_out,
    const float* __restrict__ w_pass, const float* __restrict__ b_pass,
    float* __restrict__ out)
{
    extern __shared__ uint32_t sm[];
    float* smf = reinterpret_cast<float*>(sm);

    const int tid  = threadIdx.x;
    const int lane = tid & 31;
    const int w    = tid >> 5;          // warp 0..11 -> m-tiles {w, w+12}
    const int q    = lane & 3;
    const int g    = lane >> 2;
    const int img  = blockIdx.x;
    const int imgBase = img * HW;
    const float4* x4 = reinterpret_cast<const float4*>(x);
    const uint32_t smb = (uint32_t)__cvta_generic_to_shared(sm);

    // ldmatrix per-lane offsets
    const uint32_t aFrag = (uint32_t)((lane & 15) * 36 + ((lane & 16) ? 4 : 0));
    const uint32_t bFrag = smb + 4u * (uint32_t)(OFF_B +
                           (lane & 15) * 260 + ((lane & 16) ? 4 : 0));

    // ---- prologue: one cp.async group = Bt + w_bias + A chunk 0 -------------
    // Bt: 64 rows x 64 segments of 16B = 4096 copies (FIXED from v9)
#pragma unroll
    for (int it = 0; it < 11; ++it) {
        int idx = tid + it * 384;               // 0..4223
        if (idx < 4096) {
            int row = idx >> 6, seg = idx & 63;
            cpa16(smb + (uint32_t)((OFF_B + row * 260 + seg * 4) * 4),
                  g_Bt + row * 256 + seg * 4);
        }
    }
#pragma unroll
    for (int it = 0; it < 2; ++it) {
        int idx = tid + it * 384;
        if (idx < 512)
            cpa16(smb + (uint32_t)((OFF_WB + idx * 4) * 4), w_bias + idx * 4);
    }
#pragma unroll
    for (int it = 0; it < 8; ++it) {
        int idx = tid + it * 384;               // 0..3071
        if (idx < HW * 8) {
            int r = idx >> 3, c8 = idx & 7;
            cpa16(smb + 4u * (uint32_t)(r * 36 + c8 * 4),
                  x4 + (imgBase + r) * 64 + c8);
        }
    }
    asm volatile("cp.async.commit_group;" ::: "memory");

    // zero-pad rows 361..383 of both A stages
    for (int i = tid; i < 2 * 23 * 36; i += 384) {
        int st = i / (23 * 36), rem = i % (23 * 36);
        sm[st * ASTAGE + (361 + rem / 36) * 36 + rem % 36] = 0;
    }

    if (tid < 32) {
        smf[OFF_WO + tid]      = w_out[tid * 2];
        smf[OFF_WO + 32 + tid] = w_out[tid * 2 + 1];
        smf[OFF_CG + tid] = beta_g[tid] - mean_g[tid] * rsqrtf(var_g[tid] + EPSF);
    }

    float acc[2][8][4];
#pragma unroll
    for (int m = 0; m < 2; ++m)
#pragma unroll
        for (int n = 0; n < 8; ++n)
#pragma unroll
            for (int j = 0; j < 4; ++j) acc[m][n][j] = 0.f;

    // ---- main loop: 8 K-chunks of 32, 2-stage, ONE barrier per chunk -------
    for (int c = 0; c < 8; ++c) {
        asm volatile("cp.async.wait_group 0;" ::: "memory");  // chunk c resident
        __syncthreads();   // data visible + all warps done with stage (c+1)&1

        if (c + 1 < 8) {   // overlap load(c+1) with compute(c)
            const int cc = c + 1;
            const uint32_t stage = smb + (uint32_t)(cc & 1) * (ASTAGE * 4);
#pragma unroll
            for (int it = 0; it < 8; ++it) {
                int idx = tid + it * 384;
                if (idx < HW * 8) {
                    int r = idx >> 3, c8 = idx & 7;
                    cpa16(stage + 4u * (uint32_t)(r * 36 + c8 * 4),
                          x4 + (imgBase + r) * 64 + cc * 8 + c8);
                }
            }
            asm volatile("cp.async.commit_group;" ::: "memory");
        }

        const uint32_t aBase = smb + 4u * ((uint32_t)(c & 1) * ASTAGE + aFrag);
#pragma unroll
        for (int s = 0; s < 4; ++s) {
            const uint32_t bA = bFrag + 4u * (uint32_t)(c * 32 + s * 8);
            uint32_t b0[8], b1[8];
            ldsm4(b0[0], b0[1], b1[0], b1[1], bA);                    // n 0,1
            ldsm4(b0[2], b0[3], b1[2], b1[3], bA + 4u * 16 * 260);    // n 2,3
            ldsm4(b0[4], b0[5], b1[4], b1[5], bA + 4u * 32 * 260);    // n 4,5
            ldsm4(b0[6], b0[7], b1[6], b1[7], bA + 4u * 48 * 260);    // n 6,7
#pragma unroll
            for (int m = 0; m < 2; ++m) {
                uint32_t a0, a1, a2, a3;
                ldsm4(a0, a1, a2, a3,
                      aBase + 4u * (uint32_t)((w + m * 12) * 16 * 36 + s * 8));
#pragma unroll
                for (int nt = 0; nt < 8; ++nt)
                    mma_tf32(acc[m][nt], a0, a1, a2, a3, b0[nt], b1[nt]);
            }
        }
    }

    // ---- g-branch pooling (channels live in n-tiles 4..7) --------------------
#pragma unroll
    for (int nt = 0; nt < 4; ++nt) {
#pragma unroll
        for (int j = 0; j < 2; ++j) {
            int ch = nt * 8 + 2 * q + j;
            float cg = smf[OFF_CG + ch];
            float s = 0.f, mx = 0.f;
#pragma unroll
            for (int m = 0; m < 2; ++m) {
                int r0 = (w + m * 12) * 16 + g;
                float v0 = fmaxf(acc[m][nt + 4][j] + cg, 0.f);
                float v1 = fmaxf(acc[m][nt + 4][2 + j] + cg, 0.f);
                if (r0 >= HW) v0 = 0.f;
                if (r0 + 8 >= HW) v1 = 0.f;
                s += v0 + v1;
                mx = fmaxf(mx, fmaxf(v0, v1));
            }
#pragma unroll
            for (int o = 4; o <= 16; o <<= 1) {
                s += __shfl_xor_sync(0xffffffffu, s, o);
                mx = fmaxf(mx, __shfl_xor_sync(0xffffffffu, mx, o));
            }
            if (g == 0) {
                smf[OFF_RS + w * 32 + ch] = s;
                smf[OFF_RM + w * 32 + ch] = mx;
            }
        }
    }
    __syncthreads();

    // ---- warp 0: pooled bias, cp offset, pass logits ------------------------
    if (w == 0) {
        float s = 0.f, mx = 0.f;
#pragma unroll
        for (int wi = 0; wi < 12; ++wi) {
            s += smf[OFF_RS + wi * 32 + lane];
            mx = fmaxf(mx, smf[OFF_RM + wi * 32 + lane]);
        }
        smf[OFF_POOL + lane]      = s * (1.f / 361.f);
        smf[OFF_POOL + 32 + lane] = mx;
        __syncwarp();

        float bias = b_bias[lane];
#pragma unroll
        for (int j = 0; j < 64; ++j)
            bias += smf[OFF_POOL + j] * smf[OFF_WB + j * 32 + lane];
        float ivp = rsqrtf(var_p[lane] + EPSF);
        smf[OFF_CP + lane] = (bias - mean_p[lane]) * ivp + beta_p[lane];

        if (lane < 2) {
            float pv = b_pass[lane] - 3.0f;
#pragma unroll
            for (int j = 0; j < 64; ++j)
                pv += smf[OFF_POOL + j] * w_pass[j * 2 + lane];
            out[(lane ? AUXOFF : 0) + img * OUTW + HW] = pv;
        }
    }
    __syncthreads();

    // ---- p-branch epilogue (channels live in n-tiles 0..3) -------------------
#pragma unroll
    for (int m = 0; m < 2; ++m) {
        int mt = w + m * 12;
#pragma unroll
        for (int h = 0; h < 2; ++h) {
            int r = mt * 16 + g + 8 * h;
            float p0 = 0.f, p1 = 0.f;
#pragma unroll
            for (int nt = 0; nt < 4; ++nt) {
#pragma unroll
                for (int j = 0; j < 2; ++j) {
                    int ch = nt * 8 + 2 * q + j;
                    float vv = fmaxf(acc[m][nt][2 * h + j] + smf[OFF_CP + ch], 0.f);
                    p0 += vv * smf[OFF_WO + ch];
                    p1 += vv * smf[OFF_WO + 32 + ch];
                }
            }
            p0 += __shfl_xor_sync(0xffffffffu, p0, 1);
            p0 += __shfl_xor_sync(0xffffffffu, p0, 2);
            p1 += __shfl_xor_sync(0xffffffffu, p1, 1);
            p1 += __shfl_xor_sync(0xffffffffu, p1, 2);
            if (q == 0 && r < HW) {
                out[img * OUTW + r]          = p0;
                out[AUXOFF + img * OUTW + r] = p1;
            }
        }
    }
}

extern "C" void kernel_launch(void* const* d_in, const int* in_sizes, int n_in,
                              void* d_out, int out_size) {
    (void)in_sizes; (void)n_in; (void)out_size;
    policy_init<<<64, 256>>>(
        (const float*)d_in[1], (const float*)d_in[2],
        (const float*)d_in[10], (const float*)d_in[5]);
    cudaFuncSetAttribute(policy_head_kernel,
                         cudaFuncAttributeMaxDynamicSharedMemorySize, SMEM_BYTES);
    policy_head_kernel<<<NIMG, 384, SMEM_BYTES>>>(
        (const float*)d_in[0],
        (const float*)d_in[3],  (const float*)d_in[4],  (const float*)d_in[5],
        (const float*)d_in[6],  (const float*)d_in[7],  (const float*)d_in[8],
        (const float*)d_in[9],  (const float*)d_in[10], (const float*)d_in[11],
        (const float*)d_in[12], (const float*)d_in[13],
        (float*)d_out);
}

// round 16
// speedup vs baseline: 1.2367x; 1.1588x over previous
#include <cuda_runtime.h>
#include <cstdint>

// ---------------------------------------------------------------------------
// PolicyHead fused kernel v10: one block per image, 384 threads, 12 warps.
//   y[361x64] = x[361x256] @ [w_p*ivp | w_g*ivg]   (mma.sync tf32, fp32 accum)
//   g: relu(y_g + cg) -> mean/max pool -> bias, pass logits
//   p: relu(y_p + cp) @ w_out -> pi_main / pi_aux
// A: raw fp32 via cp.async (HW truncates to tf32 in MMA); B: RNA tf32 init.
// Warp w owns m-tiles {w, w+12} AND loads their rows itself: the main loop
// has ZERO block barriers — per-warp cp.async.wait_group only. 2-stage A.
// ---------------------------------------------------------------------------

#define NIMG    2048
#define HW      361
#define OUTW    362
#define AUXOFF  (NIMG * OUTW)
#define EPSF    1e-3f

// shared memory word offsets
#define ASTAGE   13824        // one A stage: 384 rows * 36 words
#define OFF_B    27648        // Bt: 64 rows * 260 words = 16640
#define OFF_WB   44288        // 2048
#define OFF_WO   46336        // 64
#define OFF_CG   46400        // 32
#define OFF_CP   46432        // 32
#define OFF_POOL 46464        // 64
#define OFF_RS   46528        // 12*32
#define OFF_RM   46912        // 12*32
#define SMEM_WORDS 47296
#define SMEM_BYTES (SMEM_WORDS * 4)   // 189,184 B

__device__ __align__(16) uint32_t g_Bt[64 * 256];  // BN-folded, [n][k], tf32

__device__ __forceinline__ uint32_t f2tf32(float f) {
    uint32_t u;
    asm("cvt.rna.tf32.f32 %0, %1;" : "=r"(u) : "f"(f));
    return u;
}

__device__ __forceinline__ void mma_tf32(float c[4],
                                         uint32_t a0, uint32_t a1,
                                         uint32_t a2, uint32_t a3,
                                         uint32_t b0, uint32_t b1) {
    asm volatile(
        "mma.sync.aligned.m16n8k8.row.col.f32.tf32.tf32.f32 "
        "{%0,%1,%2,%3}, {%4,%5,%6,%7}, {%8,%9}, {%0,%1,%2,%3};"
        : "+f"(c[0]), "+f"(c[1]), "+f"(c[2]), "+f"(c[3])
        : "r"(a0), "r"(a1), "r"(a2), "r"(a3), "r"(b0), "r"(b1));
}

__device__ __forceinline__ void ldsm4(uint32_t& r0, uint32_t& r1,
                                      uint32_t& r2, uint32_t& r3, uint32_t addr) {
    asm volatile("ldmatrix.sync.aligned.m8n8.x4.shared.b16 {%0,%1,%2,%3}, [%4];"
                 : "=r"(r0), "=r"(r1), "=r"(r2), "=r"(r3) : "r"(addr));
}

__device__ __forceinline__ void cpa16(uint32_t dst, const void* src) {
    asm volatile("cp.async.cg.shared.global [%0], [%1], 16;"
                 :: "r"(dst), "l"(src) : "memory");
}

// ---- init: fold BN inverse-std, transpose to [n][k], convert to tf32 -------
__global__ void policy_init(const float* __restrict__ w_p,
                            const float* __restrict__ w_g,
                            const float* __restrict__ var_p,
                            const float* __restrict__ var_g) {
    int i = blockIdx.x * 256 + threadIdx.x;   // 0..16383
    int n = i >> 8, k = i & 255;
    float v = (n < 32)
        ? w_p[k * 32 + n] * rsqrtf(var_p[n] + EPSF)
        : w_g[k * 32 + (n - 32)] * rsqrtf(var_g[n - 32] + EPSF);
    g_Bt[i] = f2tf32(v);
}

__global__ void __launch_bounds__(384, 1) policy_head_kernel(
    const float* __restrict__ x,
    const float* __restrict__ beta_g, const float* __restrict__ mean_g,
    const float* __restrict__ var_g,
    const float* __restrict__ w_bias, const float* __restrict__ b_bias,
    const float* __restrict__ beta_p, const float* __restrict__ mean_p,
    const float* __restrict__ var_p,
    const float* __restrict__ w_out,
    const float* __restrict__ w_pass, const float* __restrict__ b_pass,
    float* __restrict__ out)
{
    extern __shared__ uint32_t sm[];
    float* smf = reinterpret_cast<float*>(sm);

    const int tid  = threadIdx.x;
    const int lane = tid & 31;
    const int w    = tid >> 5;          // warp 0..11 -> m-tiles {w, w+12}
    const int q    = lane & 3;
    const int g    = lane >> 2;
    const int img  = blockIdx.x;
    const int imgBase = img * HW;
    const float4* x4 = reinterpret_cast<const float4*>(x);
    const uint32_t smb = (uint32_t)__cvta_generic_to_shared(sm);

    // ldmatrix per-lane offsets
    const uint32_t aFrag = (uint32_t)((lane & 15) * 36 + ((lane & 16) ? 4 : 0));
    const uint32_t bFrag = smb + 4u * (uint32_t)(OFF_B +
                           (lane & 15) * 260 + ((lane & 16) ? 4 : 0));

    // per-warp A-row ownership for self-loading (lane -> local row, segment)
    const int lrow = lane >> 3;          // 4 local rows per lane pass
    const int lseg = lane & 7;

    // ---- prologue: one cp.async group = Bt + w_bias + A chunk 0 -------------
#pragma unroll
    for (int it = 0; it < 11; ++it) {
        int idx = tid + it * 384;               // 0..4223
        if (idx < 4096) {
            int row = idx >> 6, seg = idx & 63;
            cpa16(smb + (uint32_t)((OFF_B + row * 260 + seg * 4) * 4),
                  g_Bt + row * 256 + seg * 4);
        }
    }
#pragma unroll
    for (int it = 0; it < 2; ++it) {
        int idx = tid + it * 384;
        if (idx < 512)
            cpa16(smb + (uint32_t)((OFF_WB + idx * 4) * 4), w_bias + idx * 4);
    }
#pragma unroll
    for (int it = 0; it < 8; ++it) {
        int idx = tid + it * 384;               // 0..3071
        if (idx < HW * 8) {
            int r = idx >> 3, c8 = idx & 7;
            cpa16(smb + 4u * (uint32_t)(r * 36 + c8 * 4),
                  x4 + (imgBase + r) * 64 + c8);
        }
    }
    asm volatile("cp.async.commit_group;" ::: "memory");

    // zero-pad rows 361..383 of both A stages (plain STS, pre-barrier)
    for (int i = tid; i < 2 * 23 * 36; i += 384) {
        int st = i / (23 * 36), rem = i % (23 * 36);
        sm[st * ASTAGE + (361 + rem / 36) * 36 + rem % 36] = 0;
    }

    if (tid < 32) {
        smf[OFF_WO + tid]      = w_out[tid * 2];
        smf[OFF_WO + 32 + tid] = w_out[tid * 2 + 1];
        smf[OFF_CG + tid] = beta_g[tid] - mean_g[tid] * rsqrtf(var_g[tid] + EPSF);
    }

    float acc[2][8][4];
#pragma unroll
    for (int m = 0; m < 2; ++m)
#pragma unroll
        for (int n = 0; n < 8; ++n)
#pragma unroll
            for (int j = 0; j < 4; ++j) acc[m][n][j] = 0.f;

    asm volatile("cp.async.wait_group 0;" ::: "memory");
    __syncthreads();        // ONLY block barrier before the epilogue

    // ---- main loop: 8 K-chunks of 32, 2-stage, per-warp sync ONLY ----------
    for (int c = 0; c < 8; ++c) {
        // issue chunk c+1 for THIS WARP'S 32 rows (m-tiles w, w+12)
        if (c + 1 < 8) {
            const int cc = c + 1;
            const uint32_t stage = smb + (uint32_t)(cc & 1) * (ASTAGE * 4);
#pragma unroll
            for (int it = 0; it < 8; ++it) {
                int lr = lrow + it * 4;              // 0..31 local row
                int r = (lr < 16) ? (w * 16 + lr) : (176 + w * 16 + lr);
                if (r < HW)
                    cpa16(stage + 4u * (uint32_t)(r * 36 + lseg * 4),
                          x4 + (imgBase + r) * 64 + cc * 8 + lseg);
            }
        }
        asm volatile("cp.async.commit_group;" ::: "memory");
        asm volatile("cp.async.wait_group 1;" ::: "memory");  // chunk c resident

        const uint32_t aBase = smb + 4u * ((uint32_t)(c & 1) * ASTAGE + aFrag);
#pragma unroll
        for (int s = 0; s < 4; ++s) {
            const uint32_t bA = bFrag + 4u * (uint32_t)(c * 32 + s * 8);
            uint32_t b0[8], b1[8];
            ldsm4(b0[0], b0[1], b1[0], b1[1], bA);                    // n 0,1
            ldsm4(b0[2], b0[3], b1[2], b1[3], bA + 4u * 16 * 260);    // n 2,3
            ldsm4(b0[4], b0[5], b1[4], b1[5], bA + 4u * 32 * 260);    // n 4,5
            ldsm4(b0[6], b0[7], b1[6], b1[7], bA + 4u * 48 * 260);    // n 6,7
#pragma unroll
            for (int m = 0; m < 2; ++m) {
                uint32_t a0, a1, a2, a3;
                ldsm4(a0, a1, a2, a3,
                      aBase + 4u * (uint32_t)((w + m * 12) * 16 * 36 + s * 8));
#pragma unroll
                for (int nt = 0; nt < 8; ++nt)
                    mma_tf32(acc[m][nt], a0, a1, a2, a3, b0[nt], b1[nt]);
            }
        }
    }

    // ---- g-branch pooling (channels live in n-tiles 4..7) --------------------
#pragma unroll
    for (int nt = 0; nt < 4; ++nt) {
#pragma unroll
        for (int j = 0; j < 2; ++j) {
            int ch = nt * 8 + 2 * q + j;
            float cg = smf[OFF_CG + ch];
            float s = 0.f, mx = 0.f;
#pragma unroll
            for (int m = 0; m < 2; ++m) {
                int r0 = (w + m * 12) * 16 + g;
                float v0 = fmaxf(acc[m][nt + 4][j] + cg, 0.f);
                float v1 = fmaxf(acc[m][nt + 4][2 + j] + cg, 0.f);
                if (r0 >= HW) v0 = 0.f;
                if (r0 + 8 >= HW) v1 = 0.f;
                s += v0 + v1;
                mx = fmaxf(mx, fmaxf(v0, v1));
            }
#pragma unroll
            for (int o = 4; o <= 16; o <<= 1) {
                s += __shfl_xor_sync(0xffffffffu, s, o);
                mx = fmaxf(mx, __shfl_xor_sync(0xffffffffu, mx, o));
            }
            if (g == 0) {
                smf[OFF_RS + w * 32 + ch] = s;
                smf[OFF_RM + w * 32 + ch] = mx;
            }
        }
    }
    __syncthreads();

    // ---- warp 0: pooled bias, cp offset, pass logits ------------------------
    if (w == 0) {
        float s = 0.f, mx = 0.f;
#pragma unroll
        for (int wi = 0; wi < 12; ++wi) {
            s += smf[OFF_RS + wi * 32 + lane];
            mx = fmaxf(mx, smf[OFF_RM + wi * 32 + lane]);
        }
        smf[OFF_POOL + lane]      = s * (1.f / 361.f);
        smf[OFF_POOL + 32 + lane] = mx;
        __syncwarp();

        float bias = b_bias[lane];
#pragma unroll
        for (int j = 0; j < 64; ++j)
            bias += smf[OFF_POOL + j] * smf[OFF_WB + j * 32 + lane];
        float ivp = rsqrtf(var_p[lane] + EPSF);
        smf[OFF_CP + lane] = (bias - mean_p[lane]) * ivp + beta_p[lane];

        if (lane < 2) {
            float pv = b_pass[lane] - 3.0f;
#pragma unroll
            for (int j = 0; j < 64; ++j)
                pv += smf[OFF_POOL + j] * w_pass[j * 2 + lane];
            out[(lane ? AUXOFF : 0) + img * OUTW + HW] = pv;
        }
    }
    __syncthreads();

    // ---- p-branch epilogue (channels live in n-tiles 0..3) -------------------
#pragma unroll
    for (int m = 0; m < 2; ++m) {
        int mt = w + m * 12;
#pragma unroll
        for (int h = 0; h < 2; ++h) {
            int r = mt * 16 + g + 8 * h;
            float p0 = 0.f, p1 = 0.f;
#pragma unroll
            for (int nt = 0; nt < 4; ++nt) {
#pragma unroll
                for (int j = 0; j < 2; ++j) {
                    int ch = nt * 8 + 2 * q + j;
                    float vv = fmaxf(acc[m][nt][2 * h + j] + smf[OFF_CP + ch], 0.f);
                    p0 += vv * smf[OFF_WO + ch];
                    p1 += vv * smf[OFF_WO + 32 + ch];
                }
            }
            p0 += __shfl_xor_sync(0xffffffffu, p0, 1);
            p0 += __shfl_xor_sync(0xffffffffu, p0, 2);
            p1 += __shfl_xor_sync(0xffffffffu, p1, 1);
            p1 += __shfl_xor_sync(0xffffffffu, p1, 2);
            if (q == 0 && r < HW) {
                out[img * OUTW + r]          = p0;
                out[AUXOFF + img * OUTW + r] = p1;
            }
        }
    }
}

extern "C" void kernel_launch(void* const* d_in, const int* in_sizes, int n_in,
                              void* d_out, int out_size) {
    (void)in_sizes; (void)n_in; (void)out_size;
    policy_init<<<64, 256>>>(
        (const float*)d_in[1], (const float*)d_in[2],
        (const float*)d_in[10], (const float*)d_in[5]);
    cudaFuncSetAttribute(policy_head_kernel,
                         cudaFuncAttributeMaxDynamicSharedMemorySize, SMEM_BYTES);
    policy_head_kernel<<<NIMG, 384, SMEM_BYTES>>>(
        (const float*)d_in[0],
        (const float*)d_in[3],  (const float*)d_in[4],  (const float*)d_in[5],
        (const float*)d_in[6],  (const float*)d_in[7],  (const float*)d_in[8],
        (const float*)d_in[9],  (const float*)d_in[10], (const float*)d_in[11],
        (const float*)d_in[12], (const float*)d_in[13],
        (float*)d_out);
}

// round 17
// speedup vs baseline: 1.2453x; 1.0069x over previous
#include <cuda_runtime.h>
#include <cstdint>

// ---------------------------------------------------------------------------
// PolicyHead fused kernel v11: one block per image, 384 threads, 12 warps.
//   y[361x64] = x[361x256] @ [w_p*ivp | w_g*ivg]   (mma.sync tf32, fp32 accum)
//   g: relu(y_g + cg) -> mean/max pool -> bias, pass logits
//   p: relu(y_p + cp) @ w_out -> pi_main / pi_aux
// A: raw fp32 via cp.async (HW truncates to tf32); B: RNA tf32 init kernel.
// Warp w owns m-tiles {w, w+12} and self-loads their rows. K-chunk 16,
// 4 A stages, per-warp depth-2 pipeline: issue(c+2); commit; wait_group 2.
// ZERO block barriers in the main loop.
// ---------------------------------------------------------------------------

#define NIMG    2048
#define HW      361
#define OUTW    362
#define AUXOFF  (NIMG * OUTW)
#define EPSF    1e-3f

// shared memory word offsets
#define ASTAGE   7680         // one A stage: 384 rows * 20 words
#define OFF_B    30720        // Bt: 64 rows * 260 words = 16640
#define OFF_WB   47360        // 2048
#define OFF_WO   49408        // 64
#define OFF_CG   49472        // 32
#define OFF_CP   49504        // 32
#define OFF_POOL 49536        // 64
#define OFF_RS   49600        // 12*32
#define OFF_RM   49984        // 12*32
#define SMEM_WORDS 50368
#define SMEM_BYTES (SMEM_WORDS * 4)   // 201,472 B

__device__ __align__(16) uint32_t g_Bt[64 * 256];  // BN-folded, [n][k], tf32

__device__ __forceinline__ uint32_t f2tf32(float f) {
    uint32_t u;
    asm("cvt.rna.tf32.f32 %0, %1;" : "=r"(u) : "f"(f));
    return u;
}

__device__ __forceinline__ void mma_tf32(float c[4],
                                         uint32_t a0, uint32_t a1,
                                         uint32_t a2, uint32_t a3,
                                         uint32_t b0, uint32_t b1) {
    asm volatile(
        "mma.sync.aligned.m16n8k8.row.col.f32.tf32.tf32.f32 "
        "{%0,%1,%2,%3}, {%4,%5,%6,%7}, {%8,%9}, {%0,%1,%2,%3};"
        : "+f"(c[0]), "+f"(c[1]), "+f"(c[2]), "+f"(c[3])
        : "r"(a0), "r"(a1), "r"(a2), "r"(a3), "r"(b0), "r"(b1));
}

__device__ __forceinline__ void ldsm4(uint32_t& r0, uint32_t& r1,
                                      uint32_t& r2, uint32_t& r3, uint32_t addr) {
    asm volatile("ldmatrix.sync.aligned.m8n8.x4.shared.b16 {%0,%1,%2,%3}, [%4];"
                 : "=r"(r0), "=r"(r1), "=r"(r2), "=r"(r3) : "r"(addr));
}

__device__ __forceinline__ void cpa16(uint32_t dst, const void* src) {
    asm volatile("cp.async.cg.shared.global [%0], [%1], 16;"
                 :: "r"(dst), "l"(src) : "memory");
}

// ---- init: fold BN inverse-std, transpose to [n][k], convert to tf32 -------
__global__ void policy_init(const float* __restrict__ w_p,
                            const float* __restrict__ w_g,
                            const float* __restrict__ var_p,
                            const float* __restrict__ var_g) {
    int i = blockIdx.x * 256 + threadIdx.x;   // 0..16383
    int n = i >> 8, k = i & 255;
    float v = (n < 32)
        ? w_p[k * 32 + n] * rsqrtf(var_p[n] + EPSF)
        : w_g[k * 32 + (n - 32)] * rsqrtf(var_g[n - 32] + EPSF);
    g_Bt[i] = f2tf32(v);
}

__global__ void __launch_bounds__(384, 1) policy_head_kernel(
    const float* __restrict__ x,
    const float* __restrict__ beta_g, const float* __restrict__ mean_g,
    const float* __restrict__ var_g,
    const float* __restrict__ w_bias, const float* __restrict__ b_bias,
    const float* __restrict__ beta_p, const float* __restrict__ mean_p,
    const float* __restrict__ var_p,
    const float* __restrict__ w_out,
    const float* __restrict__ w_pass, const float* __restrict__ b_pass,
    float* __restrict__ out)
{
    extern __shared__ uint32_t sm[];
    float* smf = reinterpret_cast<float*>(sm);

    const int tid  = threadIdx.x;
    const int lane = tid & 31;
    const int w    = tid >> 5;          // warp 0..11 -> m-tiles {w, w+12}
    const int q    = lane & 3;
    const int g    = lane >> 2;
    const int img  = blockIdx.x;
    const int imgBase = img * HW;
    const float4* x4 = reinterpret_cast<const float4*>(x);
    const uint32_t smb = (uint32_t)__cvta_generic_to_shared(sm);

    // ldmatrix per-lane offsets
    const uint32_t aFrag = (uint32_t)((lane & 15) * 20 + ((lane & 16) ? 4 : 0));
    const uint32_t bFrag = smb + 4u * (uint32_t)(OFF_B +
                           (lane & 15) * 260 + ((lane & 16) ? 4 : 0));

    // per-warp self-load: lane -> 4 (row, segment) slots, pointers hoisted
    const int lrow8 = lane >> 2;        // 0..7
    const int lseg  = lane & 3;         // 0..3 (16B segments of 16 floats)
    const float4* cur[4];
    uint32_t dsto[4];
    bool     val[4];
#pragma unroll
    for (int it = 0; it < 4; ++it) {
        int lr = lrow8 + it * 8;                       // 0..31 local row
        int r = (lr < 16) ? (w * 16 + lr) : (176 + w * 16 + lr);
        val[it]  = r < HW;
        cur[it]  = x4 + (imgBase + r) * 64 + 2 * 4 + lseg;  // first issue: chunk 2
        dsto[it] = (uint32_t)(r * 20 + lseg * 4);
    }

    // ---- prologue: group0 = Bt + w_bias + chunk0; group1 = chunk1 -----------
#pragma unroll
    for (int it = 0; it < 11; ++it) {
        int idx = tid + it * 384;               // 0..4223
        if (idx < 4096) {
            int row = idx >> 6, seg = idx & 63;
            cpa16(smb + (uint32_t)((OFF_B + row * 260 + seg * 4) * 4),
                  g_Bt + row * 256 + seg * 4);
        }
    }
#pragma unroll
    for (int it = 0; it < 2; ++it) {
        int idx = tid + it * 384;
        if (idx < 512)
            cpa16(smb + (uint32_t)((OFF_WB + idx * 4) * 4), w_bias + idx * 4);
    }
#pragma unroll
    for (int it = 0; it < 4; ++it) {
        int idx = tid + it * 384;               // 0..1535
        if (idx < HW * 4) {
            int r = idx >> 2, sg = idx & 3;
            cpa16(smb + 4u * (uint32_t)(r * 20 + sg * 4),
                  x4 + (imgBase + r) * 64 + sg);
        }
    }
    asm volatile("cp.async.commit_group;" ::: "memory");
#pragma unroll
    for (int it = 0; it < 4; ++it) {
        int idx = tid + it * 384;
        if (idx < HW * 4) {
            int r = idx >> 2, sg = idx & 3;
            cpa16(smb + 4u * (uint32_t)(ASTAGE + r * 20 + sg * 4),
                  x4 + (imgBase + r) * 64 + 4 + sg);
        }
    }
    asm volatile("cp.async.commit_group;" ::: "memory");

    // zero-pad rows 361..383 of all 4 stages (cp.async never writes them)
    for (int i = tid; i < 4 * 23 * 20; i += 384) {
        int st = i / 460, rem = i % 460;
        sm[st * ASTAGE + (361 + rem / 20) * 20 + rem % 20] = 0;
    }

    if (tid < 32) {
        smf[OFF_WO + tid]      = w_out[tid * 2];
        smf[OFF_WO + 32 + tid] = w_out[tid * 2 + 1];
        smf[OFF_CG + tid] = beta_g[tid] - mean_g[tid] * rsqrtf(var_g[tid] + EPSF);
    }

    float acc[2][8][4];
#pragma unroll
    for (int m = 0; m < 2; ++m)
#pragma unroll
        for (int n = 0; n < 8; ++n)
#pragma unroll
            for (int j = 0; j < 4; ++j) acc[m][n][j] = 0.f;

    asm volatile("cp.async.wait_group 1;" ::: "memory");  // group0 (B+chunk0) done
    __syncthreads();        // ONLY block barrier before the epilogue

    // ---- main loop: 16 K-chunks of 16, per-warp depth-2 pipeline ------------
    for (int c = 0; c < 16; ++c) {
        if (c + 2 < 16) {   // issue chunk c+2 for this warp's 32 rows
            const uint32_t stage = smb + (uint32_t)((c + 2) & 3) * (ASTAGE * 4);
#pragma unroll
            for (int it = 0; it < 4; ++it) {
                if (val[it]) cpa16(stage + 4u * dsto[it], cur[it]);
                cur[it] += 4;
            }
        }
        asm volatile("cp.async.commit_group;" ::: "memory");   // uniform count
        asm volatile("cp.async.wait_group 2;" ::: "memory");   // chunk c resident

        const uint32_t aBase = smb + 4u * ((uint32_t)(c & 3) * ASTAGE + aFrag);
#pragma unroll
        for (int s = 0; s < 2; ++s) {
            const uint32_t bA = bFrag + 4u * (uint32_t)(c * 16 + s * 8);
            uint32_t b0[8], b1[8];
            ldsm4(b0[0], b0[1], b1[0], b1[1], bA);                    // n 0,1
            ldsm4(b0[2], b0[3], b1[2], b1[3], bA + 4u * 16 * 260);    // n 2,3
            ldsm4(b0[4], b0[5], b1[4], b1[5], bA + 4u * 32 * 260);    // n 4,5
            ldsm4(b0[6], b0[7], b1[6], b1[7], bA + 4u * 48 * 260);    // n 6,7
#pragma unroll
            for (int m = 0; m < 2; ++m) {
                uint32_t a0, a1, a2, a3;
                ldsm4(a0, a1, a2, a3,
                      aBase + 4u * (uint32_t)((w + m * 12) * 16 * 20 + s * 8));
#pragma unroll
                for (int nt = 0; nt < 8; ++nt)
                    mma_tf32(acc[m][nt], a0, a1, a2, a3, b0[nt], b1[nt]);
            }
        }
    }

    // ---- g-branch pooling (channels live in n-tiles 4..7) --------------------
#pragma unroll
    for (int nt = 0; nt < 4; ++nt) {
#pragma unroll
        for (int j = 0; j < 2; ++j) {
            int ch = nt * 8 + 2 * q + j;
            float cg = smf[OFF_CG + ch];
            float s = 0.f, mx = 0.f;
#pragma unroll
            for (int m = 0; m < 2; ++m) {
                int r0 = (w + m * 12) * 16 + g;
                float v0 = fmaxf(acc[m][nt + 4][j] + cg, 0.f);
                float v1 = fmaxf(acc[m][nt + 4][2 + j] + cg, 0.f);
                if (r0 >= HW) v0 = 0.f;
                if (r0 + 8 >= HW) v1 = 0.f;
                s += v0 + v1;
                mx = fmaxf(mx, fmaxf(v0, v1));
            }
#pragma unroll
            for (int o = 4; o <= 16; o <<= 1) {
                s += __shfl_xor_sync(0xffffffffu, s, o);
                mx = fmaxf(mx, __shfl_xor_sync(0xffffffffu, mx, o));
            }
            if (g == 0) {
                smf[OFF_RS + w * 32 + ch] = s;
                smf[OFF_RM + w * 32 + ch] = mx;
            }
        }
    }
    __syncthreads();

    // ---- warp 0: pooled bias, cp offset, pass logits ------------------------
    if (w == 0) {
        float s = 0.f, mx = 0.f;
#pragma unroll
        for (int wi = 0; wi < 12; ++wi) {
            s += smf[OFF_RS + wi * 32 + lane];
            mx = fmaxf(mx, smf[OFF_RM + wi * 32 + lane]);
        }
        smf[OFF_POOL + lane]      = s * (1.f / 361.f);
        smf[OFF_POOL + 32 + lane] = mx;
        __syncwarp();

        float bias = b_bias[lane];
#pragma unroll
        for (int j = 0; j < 64; ++j)
            bias += smf[OFF_POOL + j] * smf[OFF_WB + j * 32 + lane];
        float ivp = rsqrtf(var_p[lane] + EPSF);
        smf[OFF_CP + lane] = (bias - mean_p[lane]) * ivp + beta_p[lane];

        if (lane < 2) {
            float pv = b_pass[lane] - 3.0f;
#pragma unroll
            for (int j = 0; j < 64; ++j)
                pv += smf[OFF_POOL + j] * w_pass[j * 2 + lane];
            out[(lane ? AUXOFF : 0) + img * OUTW + HW] = pv;
        }
    }
    __syncthreads();

    // ---- p-branch epilogue (channels live in n-tiles 0..3) -------------------
#pragma unroll
    for (int m = 0; m < 2; ++m) {
        int mt = w + m * 12;
#pragma unroll
        for (int h = 0; h < 2; ++h) {
            int r = mt * 16 + g + 8 * h;
            float p0 = 0.f, p1 = 0.f;
#pragma unroll
            for (int nt = 0; nt < 4; ++nt) {
#pragma unroll
                for (int j = 0; j < 2; ++j) {
                    int ch = nt * 8 + 2 * q + j;
                    float vv = fmaxf(acc[m][nt][2 * h + j] + smf[OFF_CP + ch], 0.f);
                    p0 += vv * smf[OFF_WO + ch];
                    p1 += vv * smf[OFF_WO + 32 + ch];
                }
            }
            p0 += __shfl_xor_sync(0xffffffffu, p0, 1);
            p0 += __shfl_xor_sync(0xffffffffu, p0, 2);
            p1 += __shfl_xor_sync(0xffffffffu, p1, 1);
            p1 += __shfl_xor_sync(0xffffffffu, p1, 2);
            if (q == 0 && r < HW) {
                out[img * OUTW + r]          = p0;
                out[AUXOFF + img * OUTW + r] = p1;
            }
        }
    }
}

extern "C" void kernel_launch(void* const* d_in, const int* in_sizes, int n_in,
                              void* d_out, int out_size) {
    (void)in_sizes; (void)n_in; (void)out_size;
    policy_init<<<64, 256>>>(
        (const float*)d_in[1], (const float*)d_in[2],
        (const float*)d_in[10], (const float*)d_in[5]);
    cudaFuncSetAttribute(policy_head_kernel,
                         cudaFuncAttributeMaxDynamicSharedMemorySize, SMEM_BYTES);
    policy_head_kernel<<<NIMG, 384, SMEM_BYTES>>>(
        (const float*)d_in[0],
        (const float*)d_in[3],  (const float*)d_in[4],  (const float*)d_in[5],
        (const float*)d_in[6],  (const float*)d_in[7],  (const float*)d_in[8],
        (const float*)d_in[9],  (const float*)d_in[10], (const float*)d_in[11],
        (const float*)d_in[12], (const float*)d_in[13],
        (float*)d_out);
}